// round 1
// baseline (speedup 1.0000x reference)
#include <cuda_runtime.h>

#define NB     524288
#define IN_A   32
#define IN_S   32
#define DIM    64        // IN_A + IN_S
#define NE     8
#define NH     64
#define GHD    32
#define TPB    256

// shared memory layout (floats)
#define OFF_W1   0                         // NE*DIM*NH = 32768
#define OFF_GW1  (OFF_W1  + NE*DIM*NH)     // 1024
#define OFF_GW2  (OFF_GW1 + IN_S*GHD)      // 256
#define OFF_EB1  (OFF_GW2 + GHD*NE)        // 512
#define OFF_EW2  (OFF_EB1 + NE*NH)         // 512
#define OFF_GB1  (OFF_EW2 + NE*NH)         // 32
#define OFF_GB2  (OFF_GB1 + GHD)           // 8
#define OFF_EB2  (OFF_GB2 + NE)            // 8
#define OFF_X    (OFF_EB2 + NE)            // TPB*65  (stride 65: conflict-free)
#define OFF_P    (OFF_X   + TPB*65)        // TPB*9   (stride 9: conflict-free)
#define SMEM_FLOATS (OFF_P + TPB*9)
#define SMEM_BYTES  (SMEM_FLOATS * 4)      // 216256 B

__device__ __forceinline__ unsigned long long pack2(float v) {
    unsigned long long r;
    asm("mov.b64 %0, {%1, %1};" : "=l"(r) : "f"(v));
    return r;
}
__device__ __forceinline__ void ffma2(unsigned long long &acc,
                                      unsigned long long a,
                                      unsigned long long b) {
    asm("fma.rn.f32x2 %0, %1, %2, %0;" : "+l"(acc) : "l"(a), "l"(b));
}
__device__ __forceinline__ void unpack2(unsigned long long v, float &lo, float &hi) {
    asm("mov.b64 {%0, %1}, %2;" : "=f"(lo), "=f"(hi) : "l"(v));
}

__global__ void __launch_bounds__(TPB, 1)
moe_kernel(const float* __restrict__ A,  const float* __restrict__ S,
           const float* __restrict__ gw1, const float* __restrict__ gb1,
           const float* __restrict__ gw2, const float* __restrict__ gb2,
           const float* __restrict__ ew1, const float* __restrict__ eb1,
           const float* __restrict__ ew2, const float* __restrict__ eb2,
           float* __restrict__ out)
{
    extern __shared__ float sm[];
    const int tid = threadIdx.x;

    // ---- cooperative weight staging ----
    #pragma unroll 4
    for (int i = tid; i < (NE*DIM*NH)/4; i += TPB)
        ((float4*)(sm + OFF_W1))[i] = ((const float4*)ew1)[i];
    for (int i = tid; i < (IN_S*GHD)/4; i += TPB)
        ((float4*)(sm + OFF_GW1))[i] = ((const float4*)gw1)[i];
    for (int i = tid; i < (GHD*NE)/4; i += TPB)
        ((float4*)(sm + OFF_GW2))[i] = ((const float4*)gw2)[i];
    for (int i = tid; i < (NE*NH)/4; i += TPB)
        ((float4*)(sm + OFF_EB1))[i] = ((const float4*)eb1)[i];
    for (int i = tid; i < (NE*NH)/4; i += TPB)
        ((float4*)(sm + OFF_EW2))[i] = ((const float4*)ew2)[i];
    if (tid < GHD) sm[OFF_GB1 + tid] = gb1[tid];
    if (tid < NE) { sm[OFF_GB2 + tid] = gb2[tid]; sm[OFF_EB2 + tid] = eb2[tid]; }

    // ---- per-token input into padded smem (conflict-free stride 65) ----
    const long token = (long)blockIdx.x * TPB + tid;
    float* myx = sm + OFF_X + tid * 65;
    {
        const float4* Ar = (const float4*)(A + token * IN_A);
        const float4* Sr = (const float4*)(S + token * IN_S);
        #pragma unroll
        for (int i = 0; i < IN_A/4; i++) {
            float4 v = Ar[i];
            myx[4*i+0] = v.x; myx[4*i+1] = v.y; myx[4*i+2] = v.z; myx[4*i+3] = v.w;
        }
        #pragma unroll
        for (int i = 0; i < IN_S/4; i++) {
            float4 v = Sr[i];
            myx[IN_A+4*i+0] = v.x; myx[IN_A+4*i+1] = v.y;
            myx[IN_A+4*i+2] = v.z; myx[IN_A+4*i+3] = v.w;
        }
    }
    __syncthreads();

    // ---- gating MLP: relu(S @ gw1 + gb1) @ gw2 + gb2, softmax ----
    float logits[NE];
    #pragma unroll
    for (int e = 0; e < NE; e++) logits[e] = sm[OFF_GB2 + e];

    #pragma unroll 1
    for (int j = 0; j < GHD; j += 4) {
        float t[4];
        t[0] = sm[OFF_GB1 + j + 0]; t[1] = sm[OFF_GB1 + j + 1];
        t[2] = sm[OFF_GB1 + j + 2]; t[3] = sm[OFF_GB1 + j + 3];
        #pragma unroll 4
        for (int i = 0; i < IN_S; i++) {
            float sv = myx[IN_A + i];
            const float4 w = *((const float4*)(sm + OFF_GW1 + i*GHD + j));
            t[0] = fmaf(sv, w.x, t[0]); t[1] = fmaf(sv, w.y, t[1]);
            t[2] = fmaf(sv, w.z, t[2]); t[3] = fmaf(sv, w.w, t[3]);
        }
        #pragma unroll
        for (int jj = 0; jj < 4; jj++) {
            float r = fmaxf(t[jj], 0.f);
            const float* w2r = sm + OFF_GW2 + (j + jj) * NE;
            #pragma unroll
            for (int e = 0; e < NE; e++) logits[e] = fmaf(r, w2r[e], logits[e]);
        }
    }
    // softmax -> smem (padded stride 9, avoids dynamic-index reg spill later)
    {
        float m = logits[0];
        #pragma unroll
        for (int e = 1; e < NE; e++) m = fmaxf(m, logits[e]);
        float se = 0.f, p[NE];
        #pragma unroll
        for (int e = 0; e < NE; e++) { p[e] = __expf(logits[e] - m); se += p[e]; }
        float inv = 1.f / se;
        float* myp = sm + OFF_P + tid * 9;
        #pragma unroll
        for (int e = 0; e < NE; e++) myp[e] = p[e] * inv;
    }

    // ---- experts: out = sum_e p[e] * (relu(x @ W1[e] + b1[e]) . w2[e] + b2[e]) ----
    float outv = 0.f;
    const float* myp = sm + OFF_P + tid * 9;

    #pragma unroll 1
    for (int e = 0; e < NE; e++) {
        unsigned long long acc[NH/2];      // 32 packed f32x2 accumulators
        {
            const ulonglong2* bp = (const ulonglong2*)(sm + OFF_EB1 + e*NH);
            #pragma unroll
            for (int q = 0; q < NH/4; q++) {
                ulonglong2 b = bp[q];
                acc[2*q] = b.x; acc[2*q+1] = b.y;
            }
        }
        const ulonglong2* wbase = (const ulonglong2*)(sm + OFF_W1 + e*DIM*NH);
        #pragma unroll 4
        for (int d = 0; d < DIM; d++) {
            unsigned long long xd = pack2(myx[d]);
            const ulonglong2* wrow = wbase + d * (NH/4);
            #pragma unroll
            for (int q = 0; q < NH/4; q++) {
                ulonglong2 w = wrow[q];
                ffma2(acc[2*q],   xd, w.x);
                ffma2(acc[2*q+1], xd, w.y);
            }
        }
        // epilogue: relu, dot with w2, gate
        float eo = 0.f;
        const float* w2r = sm + OFF_EW2 + e*NH;
        #pragma unroll
        for (int k = 0; k < NH/2; k++) {
            float lo, hi;
            unpack2(acc[k], lo, hi);
            lo = fmaxf(lo, 0.f); hi = fmaxf(hi, 0.f);
            eo = fmaf(lo, w2r[2*k],   eo);
            eo = fmaf(hi, w2r[2*k+1], eo);
        }
        outv = fmaf(myp[e], eo + sm[OFF_EB2 + e], outv);
    }

    out[token] = outv;
}

extern "C" void kernel_launch(void* const* d_in, const int* in_sizes, int n_in,
                              void* d_out, int out_size)
{
    const float* A   = (const float*)d_in[0];
    const float* S   = (const float*)d_in[1];
    const float* gw1 = (const float*)d_in[2];
    const float* gb1 = (const float*)d_in[3];
    const float* gw2 = (const float*)d_in[4];
    const float* gb2 = (const float*)d_in[5];
    const float* ew1 = (const float*)d_in[6];
    const float* eb1 = (const float*)d_in[7];
    const float* ew2 = (const float*)d_in[8];
    const float* eb2 = (const float*)d_in[9];
    float* out = (float*)d_out;

    cudaFuncSetAttribute(moe_kernel,
                         cudaFuncAttributeMaxDynamicSharedMemorySize, SMEM_BYTES);

    const int b = in_sizes[0] / IN_A;     // 524288
    moe_kernel<<<b / TPB, TPB, SMEM_BYTES>>>(A, S, gw1, gb1, gw2, gb2,
                                             ew1, eb1, ew2, eb2, out);
}

// round 2
// speedup vs baseline: 2.9538x; 2.9538x over previous
#include <cuda_runtime.h>

#define NB        524288
#define TPB       256
#define TOK_CTA   256
#define NTILES    8          // 256 tokens / 32 per tile
#define NE        8
#define NH        64
#define DIM       64
#define GHD       32

// ---------------- PTX helpers ----------------
__device__ __forceinline__ unsigned f2tf(float f) {
    unsigned u;
    asm("cvt.rna.tf32.f32 %0, %1;" : "=r"(u) : "f"(f));
    return u;
}
__device__ __forceinline__ void mma_tf32(float* c,
                                         unsigned a0, unsigned a1, unsigned a2, unsigned a3,
                                         unsigned b0, unsigned b1) {
    asm volatile(
        "mma.sync.aligned.m16n8k8.row.col.f32.tf32.tf32.f32 "
        "{%0,%1,%2,%3}, {%4,%5,%6,%7}, {%8,%9}, {%0,%1,%2,%3};\n"
        : "+f"(c[0]), "+f"(c[1]), "+f"(c[2]), "+f"(c[3])
        : "r"(a0), "r"(a1), "r"(a2), "r"(a3), "r"(b0), "r"(b1));
}

__global__ void __launch_bounds__(TPB, 1)
moe_mma_kernel(const float* __restrict__ A,  const float* __restrict__ S,
               const float* __restrict__ gw1, const float* __restrict__ gb1,
               const float* __restrict__ gw2, const float* __restrict__ gb2,
               const float* __restrict__ ew1, const float* __restrict__ eb1,
               const float* __restrict__ ew2, const float* __restrict__ eb2,
               float* __restrict__ out)
{
    // ---- shared memory ----
    __shared__ uint4    XSv[2 * 8 * 32];     // A-frags: [(mt*8+kt)*32 + lane] -> {a0,a1,a2,a3}
    __shared__ unsigned GHu[32 * 33];        // gating hidden (tf32 bits), [token][h], pad 33
    __shared__ float    EO[32 * 9];          // per-token per-expert output (+b2)
    __shared__ float    Psm[32 * 9];         // gating probs
    __shared__ float    sw2[NE * NH];
    __shared__ float    sb1[NE * NH];
    __shared__ float    sb2[NE];

    const int tid  = threadIdx.x;
    const int w    = tid >> 5;               // warp id == expert id
    const int lane = tid & 31;
    const int g    = lane >> 2;              // groupID (rows g, g+8)
    const int tig  = lane & 3;               // threadID in group

    // ---- startup: stage small tensors ----
    for (int i = tid; i < NE * NH; i += TPB) { sw2[i] = ew2[i]; sb1[i] = eb1[i]; }
    if (tid < NE) sb2[tid] = eb2[tid];

    // ---- startup: expert B-fragments in registers (warp w = expert w) ----
    unsigned bf[8][8][2];                    // [nt][kt][2] : 128 regs
    {
        const float* we = ew1 + w * (DIM * NH);
        #pragma unroll
        for (int nt = 0; nt < 8; nt++)
            #pragma unroll
            for (int kt = 0; kt < 8; kt++) {
                bf[nt][kt][0] = f2tf(we[(kt*8 + tig    ) * NH + nt*8 + g]);
                bf[nt][kt][1] = f2tf(we[(kt*8 + tig + 4) * NH + nt*8 + g]);
            }
    }

    // ---- startup: gating fragments ----
    unsigned g1f0[4], g1f1[4]; float gbias0 = 0.f, gbias1 = 0.f;   // warps 0-3
    unsigned g2f0[4], g2f1[4]; float gb2a = 0.f, gb2b = 0.f;       // warp 4
    if (w < 4) {
        #pragma unroll
        for (int kt = 0; kt < 4; kt++) {
            g1f0[kt] = f2tf(gw1[(kt*8 + tig    ) * GHD + w*8 + g]);
            g1f1[kt] = f2tf(gw1[(kt*8 + tig + 4) * GHD + w*8 + g]);
        }
        gbias0 = gb1[w*8 + 2*tig];
        gbias1 = gb1[w*8 + 2*tig + 1];
    }
    if (w == 4) {
        #pragma unroll
        for (int kt = 0; kt < 4; kt++) {
            g2f0[kt] = f2tf(gw2[(kt*8 + tig    ) * NE + g]);
            g2f1[kt] = f2tf(gw2[(kt*8 + tig + 4) * NE + g]);
        }
        gb2a = gb2[2*tig];
        gb2b = gb2[2*tig + 1];
    }

    const int ctaBase = blockIdx.x * TOK_CTA;
    unsigned* XS = (unsigned*)XSv;

    for (int it = 0; it < NTILES; it++) {
        const int tb = ctaBase + it * 32;

        __syncthreads();   // bar1: EO/P from prev tile consumed below; XS free to rewrite

        // combine previous tile's results (threads 0-31)
        if (it > 0 && tid < 32) {
            float a = 0.f;
            #pragma unroll
            for (int e = 0; e < NE; e++)
                a = fmaf(Psm[tid*9 + e], EO[tid*9 + e], a);
            out[tb - 32 + tid] = a;
        }

        // stage 32 tokens into A-fragment-ordered smem (tf32-converted)
        #pragma unroll
        for (int j = tid; j < 512; j += TPB) {
            const int t  = j >> 4;          // token in tile (0..31)
            const int dq = j & 15;          // float4 index within the 64-dim row
            float4 v;
            if (dq < 8) v = ((const float4*)A)[(size_t)(tb + t) * 8 + dq];
            else        v = ((const float4*)S)[(size_t)(tb + t) * 8 + (dq - 8)];
            const int mt = t >> 4, ri = t & 15;
            const int gg = ri & 7, r0 = ri >> 3;
            float vv[4] = {v.x, v.y, v.z, v.w};
            #pragma unroll
            for (int c = 0; c < 4; c++) {
                const int d  = dq * 4 + c;
                const int kt = d >> 3, dk = d & 7;
                const int tg = dk & 3, r1 = dk >> 2;
                XS[((mt*8 + kt)*32 + gg*4 + tg)*4 + r0 + 2*r1] = f2tf(vv[c]);
            }
        }

        __syncthreads();   // bar2: XS ready

        // ---- gating layer 1 (warps 0-3, n-tile = w) ----
        if (w < 4) {
            #pragma unroll
            for (int mt = 0; mt < 2; mt++) {
                float ga[4] = {gbias0, gbias1, gbias0, gbias1};
                #pragma unroll
                for (int kt = 0; kt < 4; kt++) {
                    uint4 av = XSv[(mt*8 + 4 + kt)*32 + lane];
                    mma_tf32(ga, av.x, av.y, av.z, av.w, g1f0[kt], g1f1[kt]);
                }
                const int r = mt*16 + g;
                GHu[r*33     + w*8 + 2*tig    ] = f2tf(fmaxf(ga[0], 0.f));
                GHu[r*33     + w*8 + 2*tig + 1] = f2tf(fmaxf(ga[1], 0.f));
                GHu[(r+8)*33 + w*8 + 2*tig    ] = f2tf(fmaxf(ga[2], 0.f));
                GHu[(r+8)*33 + w*8 + 2*tig + 1] = f2tf(fmaxf(ga[3], 0.f));
            }
        }

        __syncthreads();   // bar3: GH ready

        // ---- gating layer 2 + softmax (warp 4) ----
        if (w == 4) {
            #pragma unroll
            for (int mt = 0; mt < 2; mt++) {
                float la[4] = {gb2a, gb2b, gb2a, gb2b};
                const int r = mt*16 + g;
                #pragma unroll
                for (int kt = 0; kt < 4; kt++) {
                    unsigned a0 = GHu[r*33     + kt*8 + tig    ];
                    unsigned a1 = GHu[(r+8)*33 + kt*8 + tig    ];
                    unsigned a2 = GHu[r*33     + kt*8 + tig + 4];
                    unsigned a3 = GHu[(r+8)*33 + kt*8 + tig + 4];
                    mma_tf32(la, a0, a1, a2, a3, g2f0[kt], g2f1[kt]);
                }
                // softmax row r over la[0],la[1] (cols 2tig,2tig+1 across 4 lanes)
                float m0 = fmaxf(la[0], la[1]);
                m0 = fmaxf(m0, __shfl_xor_sync(0xffffffffu, m0, 1));
                m0 = fmaxf(m0, __shfl_xor_sync(0xffffffffu, m0, 2));
                float e0 = __expf(la[0] - m0), e1 = __expf(la[1] - m0);
                float s0 = e0 + e1;
                s0 += __shfl_xor_sync(0xffffffffu, s0, 1);
                s0 += __shfl_xor_sync(0xffffffffu, s0, 2);
                float inv0 = 1.f / s0;
                Psm[r*9 + 2*tig    ] = e0 * inv0;
                Psm[r*9 + 2*tig + 1] = e1 * inv0;
                // softmax row r+8 over la[2],la[3]
                float m1 = fmaxf(la[2], la[3]);
                m1 = fmaxf(m1, __shfl_xor_sync(0xffffffffu, m1, 1));
                m1 = fmaxf(m1, __shfl_xor_sync(0xffffffffu, m1, 2));
                float e2 = __expf(la[2] - m1), e3 = __expf(la[3] - m1);
                float s1 = e2 + e3;
                s1 += __shfl_xor_sync(0xffffffffu, s1, 1);
                s1 += __shfl_xor_sync(0xffffffffu, s1, 2);
                float inv1 = 1.f / s1;
                Psm[(r+8)*9 + 2*tig    ] = e2 * inv1;
                Psm[(r+8)*9 + 2*tig + 1] = e3 * inv1;
            }
        }

        // ---- expert GEMM + epilogue (all 8 warps) ----
        #pragma unroll
        for (int mt = 0; mt < 2; mt++) {
            float acc[8][4];
            #pragma unroll
            for (int nt = 0; nt < 8; nt++) {
                const float2 bv = *(const float2*)(sb1 + w*NH + nt*8 + 2*tig);
                acc[nt][0] = bv.x; acc[nt][1] = bv.y;
                acc[nt][2] = bv.x; acc[nt][3] = bv.y;
            }
            #pragma unroll
            for (int kt = 0; kt < 8; kt++) {
                uint4 av = XSv[(mt*8 + kt)*32 + lane];
                #pragma unroll
                for (int nt = 0; nt < 8; nt++)
                    mma_tf32(acc[nt], av.x, av.y, av.z, av.w,
                             bf[nt][kt][0], bf[nt][kt][1]);
            }
            // relu, dot with w2 (cols 2tig,2tig+1 of each n-tile), reduce over lanes
            float pg = 0.f, ph = 0.f;
            #pragma unroll
            for (int nt = 0; nt < 8; nt++) {
                const float2 wv = *(const float2*)(sw2 + w*NH + nt*8 + 2*tig);
                pg = fmaf(fmaxf(acc[nt][0], 0.f), wv.x, pg);
                pg = fmaf(fmaxf(acc[nt][1], 0.f), wv.y, pg);
                ph = fmaf(fmaxf(acc[nt][2], 0.f), wv.x, ph);
                ph = fmaf(fmaxf(acc[nt][3], 0.f), wv.y, ph);
            }
            pg += __shfl_xor_sync(0xffffffffu, pg, 1);
            pg += __shfl_xor_sync(0xffffffffu, pg, 2);
            ph += __shfl_xor_sync(0xffffffffu, ph, 1);
            ph += __shfl_xor_sync(0xffffffffu, ph, 2);
            if (tig == 0) {
                const int r = mt*16 + g;
                EO[r*9 + w]     = pg + sb2[w];
                EO[(r+8)*9 + w] = ph + sb2[w];
            }
        }
    }

    __syncthreads();
    if (tid < 32) {
        float a = 0.f;
        #pragma unroll
        for (int e = 0; e < NE; e++)
            a = fmaf(Psm[tid*9 + e], EO[tid*9 + e], a);
        out[ctaBase + 7*32 + tid] = a;
    }
}

extern "C" void kernel_launch(void* const* d_in, const int* in_sizes, int n_in,
                              void* d_out, int out_size)
{
    const float* A   = (const float*)d_in[0];
    const float* S   = (const float*)d_in[1];
    const float* gw1 = (const float*)d_in[2];
    const float* gb1 = (const float*)d_in[3];
    const float* gw2 = (const float*)d_in[4];
    const float* gb2 = (const float*)d_in[5];
    const float* ew1 = (const float*)d_in[6];
    const float* eb1 = (const float*)d_in[7];
    const float* ew2 = (const float*)d_in[8];
    const float* eb2 = (const float*)d_in[9];
    float* out = (float*)d_out;

    const int b = in_sizes[0] / 32;          // 524288 tokens
    moe_mma_kernel<<<b / TOK_CTA, TPB>>>(A, S, gw1, gb1, gw2, gb2,
                                         ew1, eb1, ew2, eb2, out);
}